// round 10
// baseline (speedup 1.0000x reference)
#include <cuda_runtime.h>
#include <math.h>

#define BINSIZE      200
#define BINWIDTH     500
#define N_CLUSTERS   20
#define N_ROI_MAX    200
#define N_FRAG_MAX   2000000

// Precomputed log-density table: [n_roi, n_clusters, BINWIDTH]  (8MB)
__device__ float g_heights[N_ROI_MAX * N_CLUSTERS * BINWIDTH];
// Per-fragment packed index: (heights_index << 1) | match   (8MB)
__device__ __align__(16) int g_packed[N_FRAG_MAX + 16];

// ---------------------------------------------------------------------------
// Kernel 1 (fused, two block ranges):
//   [0, rowBlocks)  : heights build (one warp per (roi,cluster) row)
//   [rowBlocks, ..) : fuse phase — per fragment, resolve label gather and
//                     bin computation into a packed heights index + match bit.
// ---------------------------------------------------------------------------
__global__ void __launch_bounds__(256) build_fuse_kernel(
    const float* __restrict__ baseline,
    const float* __restrict__ delta,
    const int*   __restrict__ regions_oi,
    const int*   __restrict__ labels,     // [n_cells] int32
    const int*   __restrict__ coords,     // [n,2]
    const int*   __restrict__ lrix,       // [n]
    const int*   __restrict__ lcix,       // [n]
    int n_rows, int n_clusters, int rowBlocks, int n)
{
    if ((int)blockIdx.x < rowBlocks) {
        const int warp = (int)blockIdx.x * 8 + ((int)threadIdx.x >> 5);
        if (warp >= n_rows) return;
        const int lane = threadIdx.x & 31;
        const int roi = warp / n_clusters;
        const int cl  = warp - roi * n_clusters;
        const int region = regions_oi[roi];

        const float4* __restrict__ b4 = (const float4*)(baseline + (long long)region * BINWIDTH);
        const float4* __restrict__ d4 = (const float4*)(delta + ((long long)region * n_clusters + cl) * BINWIDTH);

        float4 v[4];
        float m = -INFINITY;
        #pragma unroll
        for (int it = 0; it < 4; it++) {
            const int idx = lane + it * 32;
            if (idx < 125) {
                float4 a = b4[idx];
                float4 d = d4[idx];
                v[it].x = a.x + d.x; v[it].y = a.y + d.y;
                v[it].z = a.z + d.z; v[it].w = a.w + d.w;
                m = fmaxf(m, fmaxf(fmaxf(v[it].x, v[it].y), fmaxf(v[it].z, v[it].w)));
            }
        }
        #pragma unroll
        for (int o = 16; o > 0; o >>= 1)
            m = fmaxf(m, __shfl_xor_sync(0xffffffffu, m, o));

        float s = 0.0f;
        #pragma unroll
        for (int it = 0; it < 4; it++) {
            const int idx = lane + it * 32;
            if (idx < 125) {
                s += __expf(v[it].x - m) + __expf(v[it].y - m)
                   + __expf(v[it].z - m) + __expf(v[it].w - m);
            }
        }
        #pragma unroll
        for (int o = 16; o > 0; o >>= 1)
            s += __shfl_xor_sync(0xffffffffu, s, o);

        const float sub = m + __logf(s) + logf((float)BINSIZE);

        float4* __restrict__ o4 = (float4*)(g_heights + (long long)warp * BINWIDTH);
        #pragma unroll
        for (int it = 0; it < 4; it++) {
            const int idx = lane + it * 32;
            if (idx < 125) {
                float4 h;
                h.x = v[it].x - sub; h.y = v[it].y - sub;
                h.z = v[it].z - sub; h.w = v[it].w - sub;
                o4[idx] = h;
            }
        }
    } else {
        // Fuse phase: 4 fragments per thread.
        const int g = ((int)blockIdx.x - rowBlocks) * 256 + (int)threadIdx.x;
        const int i0 = g * 4;
        if (i0 >= n) return;

        if (i0 + 4 <= n) {
            const int4 c0 = __ldcs((const int4*)coords + g * 2 + 0);
            const int4 c1 = __ldcs((const int4*)coords + g * 2 + 1);
            const int4 rr = __ldcs((const int4*)lrix + g);
            const int4 qq = __ldcs((const int4*)lcix + g);

            const int lab0 = __ldg(&labels[qq.x]);
            const int lab1 = __ldg(&labels[qq.y]);
            const int lab2 = __ldg(&labels[qq.z]);
            const int lab3 = __ldg(&labels[qq.w]);

            const int bl0 = (int)((unsigned)c0.x / BINSIZE), br0 = (int)((unsigned)c0.y / BINSIZE);
            const int bl1 = (int)((unsigned)c0.z / BINSIZE), br1 = (int)((unsigned)c0.w / BINSIZE);
            const int bl2 = (int)((unsigned)c1.x / BINSIZE), br2 = (int)((unsigned)c1.y / BINSIZE);
            const int bl3 = (int)((unsigned)c1.z / BINSIZE), br3 = (int)((unsigned)c1.w / BINSIZE);

            int4 pk;
            pk.x = (((rr.x * n_clusters + lab0) * BINWIDTH + bl0) << 1) | (bl0 == br0 ? 1 : 0);
            pk.y = (((rr.y * n_clusters + lab1) * BINWIDTH + bl1) << 1) | (bl1 == br1 ? 1 : 0);
            pk.z = (((rr.z * n_clusters + lab2) * BINWIDTH + bl2) << 1) | (bl2 == br2 ? 1 : 0);
            pk.w = (((rr.w * n_clusters + lab3) * BINWIDTH + bl3) << 1) | (bl3 == br3 ? 1 : 0);
            __stcg((int4*)g_packed + g, pk);   // default policy: stay in L2 for k2
        } else {
            for (int i = i0; i < n; i++) {
                const int cx = coords[i * 2 + 0];
                const int cy = coords[i * 2 + 1];
                const int bl = (int)((unsigned)cx / BINSIZE), br = (int)((unsigned)cy / BINSIZE);
                const int lab = labels[lcix[i]];
                const int rg = lrix[i];
                g_packed[i] = (((rg * n_clusters + lab) * BINWIDTH + bl) << 1) | (bl == br ? 1 : 0);
            }
        }
    }
}

// ---------------------------------------------------------------------------
// Kernel 2: one-deep gather. Load packed index (L2-hot), gather heights,
// write output. 4 fragments/thread.
// ---------------------------------------------------------------------------
__global__ void __launch_bounds__(256) gather2_kernel(
    const float* __restrict__ inside,
    float*       __restrict__ out,         // [n, 2]
    int n)
{
    const int g  = blockIdx.x * blockDim.x + threadIdx.x;
    const int i0 = g * 4;
    if (i0 >= n) return;

    const float x    = inside[0];
    const float l1p  = log1pf(expf(-x));
    const float lpIn  = -l1p     - logf((float)BINWIDTH);
    const float lpOut = -x - l1p - logf((float)(100000 - BINWIDTH));

    if (i0 + 4 <= n) {
        const int4 p = __ldcg((const int4*)g_packed + g);

        const float L0 = __ldg(&g_heights[p.x >> 1]);
        const float L1 = __ldg(&g_heights[p.y >> 1]);
        const float L2 = __ldg(&g_heights[p.z >> 1]);
        const float L3 = __ldg(&g_heights[p.w >> 1]);

        float4 o0, o1;
        o0.x = L0; o0.y = (p.x & 1) ? lpIn : lpOut;
        o0.z = L1; o0.w = (p.y & 1) ? lpIn : lpOut;
        o1.x = L2; o1.y = (p.z & 1) ? lpIn : lpOut;
        o1.z = L3; o1.w = (p.w & 1) ? lpIn : lpOut;
        __stcs((float4*)out + g * 2 + 0, o0);
        __stcs((float4*)out + g * 2 + 1, o1);
    } else {
        for (int i = i0; i < n; i++) {
            const int p = g_packed[i];
            out[i * 2 + 0] = g_heights[p >> 1];
            out[i * 2 + 1] = (p & 1) ? lpIn : lpOut;
        }
    }
}

// Fallback for n > N_FRAG_MAX: combined gather reading inputs directly.
__global__ void __launch_bounds__(256) gather_fallback_kernel(
    const int*   __restrict__ coords,
    const int*   __restrict__ lrix,
    const int*   __restrict__ lcix,
    const int*   __restrict__ labels,
    const float* __restrict__ inside,
    float*       __restrict__ out,
    int n, int n_clusters)
{
    const int i = blockIdx.x * blockDim.x + threadIdx.x;
    if (i >= n) return;
    const float x    = inside[0];
    const float l1p  = log1pf(expf(-x));
    const float lpIn  = -l1p     - logf((float)BINWIDTH);
    const float lpOut = -x - l1p - logf((float)(100000 - BINWIDTH));
    const int cx = coords[i * 2 + 0];
    const int cy = coords[i * 2 + 1];
    const int bl = (int)((unsigned)cx / BINSIZE), br = (int)((unsigned)cy / BINSIZE);
    const int lab = labels[lcix[i]];
    const int rg = lrix[i];
    out[i * 2 + 0] = g_heights[(rg * n_clusters + lab) * BINWIDTH + bl];
    out[i * 2 + 1] = (bl == br) ? lpIn : lpOut;
}

// ---------------------------------------------------------------------------
extern "C" void kernel_launch(void* const* d_in, const int* in_sizes, int n_in,
                              void* d_out, int out_size)
{
    const float* baseline = (const float*)d_in[0];
    const float* delta    = (const float*)d_in[1];
    const float* inside   = (const float*)d_in[2];
    const int*   regions  = (const int*)d_in[3];
    const int*   coords   = (const int*)d_in[4];
    const int*   lrix     = (const int*)d_in[5];
    const int*   lcix     = (const int*)d_in[6];
    const int*   labels   = (const int*)d_in[7];
    float*       out      = (float*)d_out;

    const int n_roi      = in_sizes[3];
    const int n          = in_sizes[5];
    const int n_regions  = in_sizes[0] / BINWIDTH;
    const int n_clusters = (n_regions > 0) ? (in_sizes[1] / (n_regions * BINWIDTH)) : N_CLUSTERS;

    const int n_rows    = n_roi * n_clusters;
    const int rowBlocks = (n_rows + 7) / 8;

    if (n <= N_FRAG_MAX) {
        const int n_groups   = (n + 3) / 4;
        const int fuseBlocks = (n_groups + 255) / 256;
        build_fuse_kernel<<<rowBlocks + fuseBlocks, 256>>>(
            baseline, delta, regions, labels, coords, lrix, lcix,
            n_rows, n_clusters, rowBlocks, n);
        gather2_kernel<<<fuseBlocks, 256>>>(inside, out, n);
    } else {
        build_fuse_kernel<<<rowBlocks, 256>>>(
            baseline, delta, regions, labels, coords, lrix, lcix,
            n_rows, n_clusters, rowBlocks, 0);
        const int blocks = (n + 255) / 256;
        gather_fallback_kernel<<<blocks, 256>>>(
            coords, lrix, lcix, labels, inside, out, n, n_clusters);
    }
}

// round 11
// speedup vs baseline: 1.3810x; 1.3810x over previous
#include <cuda_runtime.h>
#include <math.h>

#define BINSIZE      200
#define BINWIDTH     500
#define N_CLUSTERS   20
#define N_ROI_MAX    200
#define N_CELLS_MAX  100352   // 100000 rounded up to 16B multiple

// Precomputed log-density table: [n_roi, n_clusters, BINWIDTH]  (8MB)
__device__ float g_heights[N_ROI_MAX * N_CLUSTERS * BINWIDTH];
// labels compacted to uint8 (100KB -> L1-resident)
__device__ __align__(16) unsigned char g_labels8[N_CELLS_MAX];

// ---------------------------------------------------------------------------
// Kernel 1 (fused): heights build (warp per row) + label int32->uint8 pack.
// Triggers programmatic launch completion at block start so the gather
// kernel can begin its stream-load preamble while this kernel runs.
// ---------------------------------------------------------------------------
__global__ void __launch_bounds__(256) build_kernel(
    const float* __restrict__ baseline,
    const float* __restrict__ delta,
    const int*   __restrict__ regions_oi,
    const int*   __restrict__ labels,
    int n_rows, int n_clusters, int rowBlocks, int n_cells)
{
#if __CUDA_ARCH__ >= 900
    cudaTriggerProgrammaticLaunchCompletion();
#endif
    if ((int)blockIdx.x < rowBlocks) {
        const int warp = (int)blockIdx.x * 8 + ((int)threadIdx.x >> 5);
        if (warp >= n_rows) return;
        const int lane = threadIdx.x & 31;
        const int roi = warp / n_clusters;
        const int cl  = warp - roi * n_clusters;
        const int region = regions_oi[roi];

        const float4* __restrict__ b4 = (const float4*)(baseline + (long long)region * BINWIDTH);
        const float4* __restrict__ d4 = (const float4*)(delta + ((long long)region * n_clusters + cl) * BINWIDTH);

        float4 v[4];
        float m = -INFINITY;
        #pragma unroll
        for (int it = 0; it < 4; it++) {
            const int idx = lane + it * 32;
            if (idx < 125) {
                float4 a = b4[idx];
                float4 d = d4[idx];
                v[it].x = a.x + d.x; v[it].y = a.y + d.y;
                v[it].z = a.z + d.z; v[it].w = a.w + d.w;
                m = fmaxf(m, fmaxf(fmaxf(v[it].x, v[it].y), fmaxf(v[it].z, v[it].w)));
            }
        }
        #pragma unroll
        for (int o = 16; o > 0; o >>= 1)
            m = fmaxf(m, __shfl_xor_sync(0xffffffffu, m, o));

        float s = 0.0f;
        #pragma unroll
        for (int it = 0; it < 4; it++) {
            const int idx = lane + it * 32;
            if (idx < 125) {
                s += __expf(v[it].x - m) + __expf(v[it].y - m)
                   + __expf(v[it].z - m) + __expf(v[it].w - m);
            }
        }
        #pragma unroll
        for (int o = 16; o > 0; o >>= 1)
            s += __shfl_xor_sync(0xffffffffu, s, o);

        const float sub = m + __logf(s) + logf((float)BINSIZE);

        float4* __restrict__ o4 = (float4*)(g_heights + (long long)warp * BINWIDTH);
        #pragma unroll
        for (int it = 0; it < 4; it++) {
            const int idx = lane + it * 32;
            if (idx < 125) {
                float4 h;
                h.x = v[it].x - sub; h.y = v[it].y - sub;
                h.z = v[it].z - sub; h.w = v[it].w - sub;
                o4[idx] = h;
            }
        }
    } else {
        const int b = (int)blockIdx.x - rowBlocks;
        const int t = b * 256 + (int)threadIdx.x;
        const int i0 = t * 4;
        if (i0 + 4 <= n_cells) {
            const int4 l = ((const int4*)labels)[t];
            uchar4 p;
            p.x = (unsigned char)l.x; p.y = (unsigned char)l.y;
            p.z = (unsigned char)l.z; p.w = (unsigned char)l.w;
            ((uchar4*)g_labels8)[t] = p;
        } else {
            for (int i = i0; i < n_cells; i++)
                g_labels8[i] = (unsigned char)labels[i];
        }
    }
}

// ---------------------------------------------------------------------------
// Kernel 2: gather, warp-cooperative layout. Each warp owns 128 consecutive
// fragments = 64 consecutive 16B vectors of coords/out and 64 int2 of
// lrix/lcix; thread L takes vec (vbase+L) and (vbase+32+L) so every
// streaming load/store instruction is lane-contiguous (halves their
// wavefront count vs stride-2). Preamble (streams + bin math) runs before
// cudaGridDependencySynchronize() -> overlaps with build under PDL.
// ---------------------------------------------------------------------------
__global__ void __launch_bounds__(256) gather_kernel(
    const int*   __restrict__ coords,      // [n, 2]
    const int*   __restrict__ lrix,        // [n]
    const int*   __restrict__ lcix,        // [n]
    const float* __restrict__ inside,      // [1]
    float*       __restrict__ out,         // [n, 2]
    int n)
{
    const int warp_g = (blockIdx.x * blockDim.x + threadIdx.x) >> 5;
    const int lane   = threadIdx.x & 31;
    const int fbase  = warp_g * 128;

    // constants from input (independent of build outputs)
    const float x    = inside[0];
    const float l1p  = log1pf(expf(-x));
    const float lpIn  = -l1p     - logf((float)BINWIDTH);
    const float lpOut = -x - l1p - logf((float)(100000 - BINWIDTH));

    if (fbase >= n) {
#if __CUDA_ARCH__ >= 900
        cudaGridDependencySynchronize();
#endif
        return;
    }

    if (fbase + 128 <= n) {
        const int vbase = warp_g * 64;
        // ---- preamble: streaming loads (coalesced), bin math ----
        const int4 cv0 = __ldcs((const int4*)coords + vbase + lane);        // frags pA, pA+1
        const int4 cv1 = __ldcs((const int4*)coords + vbase + 32 + lane);   // frags pB, pB+1
        const int2 q01 = __ldcs((const int2*)lcix + vbase + lane);
        const int2 q23 = __ldcs((const int2*)lcix + vbase + 32 + lane);
        const int2 r01 = __ldcs((const int2*)lrix + vbase + lane);
        const int2 r23 = __ldcs((const int2*)lrix + vbase + 32 + lane);

        const int bl0 = (int)((unsigned)cv0.x / BINSIZE), br0 = (int)((unsigned)cv0.y / BINSIZE);
        const int bl1 = (int)((unsigned)cv0.z / BINSIZE), br1 = (int)((unsigned)cv0.w / BINSIZE);
        const int bl2 = (int)((unsigned)cv1.x / BINSIZE), br2 = (int)((unsigned)cv1.y / BINSIZE);
        const int bl3 = (int)((unsigned)cv1.z / BINSIZE), br3 = (int)((unsigned)cv1.w / BINSIZE);

        // ---- wait for build kernel's tables ----
#if __CUDA_ARCH__ >= 900
        cudaGridDependencySynchronize();
#endif

        const int lab0 = __ldg(&g_labels8[q01.x]);
        const int lab1 = __ldg(&g_labels8[q01.y]);
        const int lab2 = __ldg(&g_labels8[q23.x]);
        const int lab3 = __ldg(&g_labels8[q23.y]);

        const float L0 = __ldg(&g_heights[(r01.x * N_CLUSTERS + lab0) * BINWIDTH + bl0]);
        const float L1 = __ldg(&g_heights[(r01.y * N_CLUSTERS + lab1) * BINWIDTH + bl1]);
        const float L2 = __ldg(&g_heights[(r23.x * N_CLUSTERS + lab2) * BINWIDTH + bl2]);
        const float L3 = __ldg(&g_heights[(r23.y * N_CLUSTERS + lab3) * BINWIDTH + bl3]);

        float4 o0, o1;
        o0.x = L0; o0.y = (bl0 == br0) ? lpIn : lpOut;
        o0.z = L1; o0.w = (bl1 == br1) ? lpIn : lpOut;
        o1.x = L2; o1.y = (bl2 == br2) ? lpIn : lpOut;
        o1.z = L3; o1.w = (bl3 == br3) ? lpIn : lpOut;
        __stcs((float4*)out + vbase + lane,      o0);
        __stcs((float4*)out + vbase + 32 + lane, o1);
    } else {
        // tail warp: scalar per-fragment
#if __CUDA_ARCH__ >= 900
        cudaGridDependencySynchronize();
#endif
        for (int i = fbase + lane; i < n; i += 32) {
            const int cx = coords[i * 2 + 0];
            const int cy = coords[i * 2 + 1];
            const int bl = (int)((unsigned)cx / BINSIZE), br = (int)((unsigned)cy / BINSIZE);
            const int lab = g_labels8[lcix[i]];
            const int rg = lrix[i];
            out[i * 2 + 0] = g_heights[(rg * N_CLUSTERS + lab) * BINWIDTH + bl];
            out[i * 2 + 1] = (bl == br) ? lpIn : lpOut;
        }
    }
}

// ---------------------------------------------------------------------------
extern "C" void kernel_launch(void* const* d_in, const int* in_sizes, int n_in,
                              void* d_out, int out_size)
{
    const float* baseline = (const float*)d_in[0];
    const float* delta    = (const float*)d_in[1];
    const float* inside   = (const float*)d_in[2];
    const int*   regions  = (const int*)d_in[3];
    const int*   coords   = (const int*)d_in[4];
    const int*   lrix     = (const int*)d_in[5];
    const int*   lcix     = (const int*)d_in[6];
    const int*   labels   = (const int*)d_in[7];
    float*       out      = (float*)d_out;

    const int n_roi      = in_sizes[3];
    const int n          = in_sizes[5];
    const int n_cells    = in_sizes[7];
    const int n_regions  = in_sizes[0] / BINWIDTH;
    const int n_clusters = (n_regions > 0) ? (in_sizes[1] / (n_regions * BINWIDTH)) : N_CLUSTERS;

    const int n_rows     = n_roi * n_clusters;
    const int rowBlocks  = (n_rows + 7) / 8;
    const int packBlocks = (n_cells + 1023) / 1024;
    build_kernel<<<rowBlocks + packBlocks, 256>>>(
        baseline, delta, regions, labels, n_rows, n_clusters, rowBlocks, n_cells);

    const int warps  = (n + 127) / 128;
    const int blocks = (warps + 7) / 8;       // 8 warps (256 threads) per block

    // Launch gather with Programmatic Dependent Launch so its stream-load
    // preamble overlaps the build kernel.
    cudaLaunchConfig_t cfg = {};
    cfg.gridDim  = dim3((unsigned)blocks, 1, 1);
    cfg.blockDim = dim3(256, 1, 1);
    cfg.dynamicSmemBytes = 0;
    cfg.stream = 0;
    cudaLaunchAttribute at[1];
    at[0].id = cudaLaunchAttributeProgrammaticStreamSerialization;
    at[0].val.programmaticStreamSerializationAllowed = 1;
    cfg.attrs = at;
    cfg.numAttrs = 1;
    cudaError_t e = cudaLaunchKernelEx(&cfg, gather_kernel,
                                       coords, lrix, lcix, inside, out, n);
    if (e != cudaSuccess) {
        // fallback: plain serialized launch
        gather_kernel<<<blocks, 256>>>(coords, lrix, lcix, inside, out, n);
    }
}

// round 12
// speedup vs baseline: 1.3944x; 1.0097x over previous
#include <cuda_runtime.h>
#include <math.h>

#define BINSIZE      200
#define BINWIDTH     500
#define N_CLUSTERS   20
#define N_ROI_MAX    200
#define N_CELLS_MAX  100352   // 100000 rounded up to 16B multiple

// Precomputed log-density table: [n_roi, n_clusters, BINWIDTH]  (8MB)
__device__ float g_heights[N_ROI_MAX * N_CLUSTERS * BINWIDTH];
// labels compacted to uint8 (100KB -> L1-resident)
__device__ __align__(16) unsigned char g_labels8[N_CELLS_MAX];

// ---------------------------------------------------------------------------
// Kernel 1 (fused): heights build (warp per row) + label int32->uint8 pack.
// Triggers programmatic launch completion at block start so the gather
// kernel can begin its stream-load preamble while this kernel runs.
// ---------------------------------------------------------------------------
__global__ void __launch_bounds__(256) build_kernel(
    const float* __restrict__ baseline,
    const float* __restrict__ delta,
    const int*   __restrict__ regions_oi,
    const int*   __restrict__ labels,
    int n_rows, int n_clusters, int rowBlocks, int n_cells)
{
#if __CUDA_ARCH__ >= 900
    cudaTriggerProgrammaticLaunchCompletion();
#endif
    if ((int)blockIdx.x < rowBlocks) {
        const int warp = (int)blockIdx.x * 8 + ((int)threadIdx.x >> 5);
        if (warp >= n_rows) return;
        const int lane = threadIdx.x & 31;
        const int roi = warp / n_clusters;
        const int cl  = warp - roi * n_clusters;
        const int region = regions_oi[roi];

        const float4* __restrict__ b4 = (const float4*)(baseline + (long long)region * BINWIDTH);
        const float4* __restrict__ d4 = (const float4*)(delta + ((long long)region * n_clusters + cl) * BINWIDTH);

        float4 v[4];
        float m = -INFINITY;
        #pragma unroll
        for (int it = 0; it < 4; it++) {
            const int idx = lane + it * 32;
            if (idx < 125) {
                float4 a = b4[idx];
                float4 d = d4[idx];
                v[it].x = a.x + d.x; v[it].y = a.y + d.y;
                v[it].z = a.z + d.z; v[it].w = a.w + d.w;
                m = fmaxf(m, fmaxf(fmaxf(v[it].x, v[it].y), fmaxf(v[it].z, v[it].w)));
            }
        }
        #pragma unroll
        for (int o = 16; o > 0; o >>= 1)
            m = fmaxf(m, __shfl_xor_sync(0xffffffffu, m, o));

        float s = 0.0f;
        #pragma unroll
        for (int it = 0; it < 4; it++) {
            const int idx = lane + it * 32;
            if (idx < 125) {
                s += __expf(v[it].x - m) + __expf(v[it].y - m)
                   + __expf(v[it].z - m) + __expf(v[it].w - m);
            }
        }
        #pragma unroll
        for (int o = 16; o > 0; o >>= 1)
            s += __shfl_xor_sync(0xffffffffu, s, o);

        const float sub = m + __logf(s) + logf((float)BINSIZE);

        float4* __restrict__ o4 = (float4*)(g_heights + (long long)warp * BINWIDTH);
        #pragma unroll
        for (int it = 0; it < 4; it++) {
            const int idx = lane + it * 32;
            if (idx < 125) {
                float4 h;
                h.x = v[it].x - sub; h.y = v[it].y - sub;
                h.z = v[it].z - sub; h.w = v[it].w - sub;
                o4[idx] = h;
            }
        }
    } else {
        const int b = (int)blockIdx.x - rowBlocks;
        const int t = b * 256 + (int)threadIdx.x;
        const int i0 = t * 4;
        if (i0 + 4 <= n_cells) {
            const int4 l = ((const int4*)labels)[t];
            uchar4 p;
            p.x = (unsigned char)l.x; p.y = (unsigned char)l.y;
            p.z = (unsigned char)l.z; p.w = (unsigned char)l.w;
            ((uchar4*)g_labels8)[t] = p;
        } else {
            for (int i = i0; i < n_cells; i++)
                g_labels8[i] = (unsigned char)labels[i];
        }
    }
}

// ---------------------------------------------------------------------------
// Kernel 2: gather, warp-cooperative lane-contiguous layout (128 frags/warp).
// Cache routing: labels8 gathers allocate in L1 (table is 100KB and should
// stay resident); heights gathers use __ldcg (L1 bypass, L2-cached) so they
// don't thrash the labels table out of L1. Streams use .cs evict-first.
// Preamble overlaps the build kernel via PDL.
// ---------------------------------------------------------------------------
__global__ void __launch_bounds__(256) gather_kernel(
    const int*   __restrict__ coords,      // [n, 2]
    const int*   __restrict__ lrix,        // [n]
    const int*   __restrict__ lcix,        // [n]
    const float* __restrict__ inside,      // [1]
    float*       __restrict__ out,         // [n, 2]
    int n)
{
    const int warp_g = (blockIdx.x * blockDim.x + threadIdx.x) >> 5;
    const int lane   = threadIdx.x & 31;
    const int fbase  = warp_g * 128;

    const float x    = inside[0];
    const float l1p  = log1pf(expf(-x));
    const float lpIn  = -l1p     - logf((float)BINWIDTH);
    const float lpOut = -x - l1p - logf((float)(100000 - BINWIDTH));

    if (fbase >= n) {
#if __CUDA_ARCH__ >= 900
        cudaGridDependencySynchronize();
#endif
        return;
    }

    if (fbase + 128 <= n) {
        const int vbase = warp_g * 64;
        // ---- preamble: streaming loads (coalesced), bin math ----
        const int4 cv0 = __ldcs((const int4*)coords + vbase + lane);
        const int4 cv1 = __ldcs((const int4*)coords + vbase + 32 + lane);
        const int2 q01 = __ldcs((const int2*)lcix + vbase + lane);
        const int2 q23 = __ldcs((const int2*)lcix + vbase + 32 + lane);
        const int2 r01 = __ldcs((const int2*)lrix + vbase + lane);
        const int2 r23 = __ldcs((const int2*)lrix + vbase + 32 + lane);

        const int bl0 = (int)((unsigned)cv0.x / BINSIZE), br0 = (int)((unsigned)cv0.y / BINSIZE);
        const int bl1 = (int)((unsigned)cv0.z / BINSIZE), br1 = (int)((unsigned)cv0.w / BINSIZE);
        const int bl2 = (int)((unsigned)cv1.x / BINSIZE), br2 = (int)((unsigned)cv1.y / BINSIZE);
        const int bl3 = (int)((unsigned)cv1.z / BINSIZE), br3 = (int)((unsigned)cv1.w / BINSIZE);

        // ---- wait for build kernel's tables ----
#if __CUDA_ARCH__ >= 900
        cudaGridDependencySynchronize();
#endif

        // label gathers: L1-allocating (table stays resident)
        const int lab0 = __ldg(&g_labels8[q01.x]);
        const int lab1 = __ldg(&g_labels8[q01.y]);
        const int lab2 = __ldg(&g_labels8[q23.x]);
        const int lab3 = __ldg(&g_labels8[q23.y]);

        // heights gathers: L1 bypass, L2-cached (don't thrash labels in L1)
        const float L0 = __ldcg(&g_heights[(r01.x * N_CLUSTERS + lab0) * BINWIDTH + bl0]);
        const float L1 = __ldcg(&g_heights[(r01.y * N_CLUSTERS + lab1) * BINWIDTH + bl1]);
        const float L2 = __ldcg(&g_heights[(r23.x * N_CLUSTERS + lab2) * BINWIDTH + bl2]);
        const float L3 = __ldcg(&g_heights[(r23.y * N_CLUSTERS + lab3) * BINWIDTH + bl3]);

        float4 o0, o1;
        o0.x = L0; o0.y = (bl0 == br0) ? lpIn : lpOut;
        o0.z = L1; o0.w = (bl1 == br1) ? lpIn : lpOut;
        o1.x = L2; o1.y = (bl2 == br2) ? lpIn : lpOut;
        o1.z = L3; o1.w = (bl3 == br3) ? lpIn : lpOut;
        __stcs((float4*)out + vbase + lane,      o0);
        __stcs((float4*)out + vbase + 32 + lane, o1);
    } else {
        // tail warp: scalar per-fragment
#if __CUDA_ARCH__ >= 900
        cudaGridDependencySynchronize();
#endif
        for (int i = fbase + lane; i < n; i += 32) {
            const int cx = coords[i * 2 + 0];
            const int cy = coords[i * 2 + 1];
            const int bl = (int)((unsigned)cx / BINSIZE), br = (int)((unsigned)cy / BINSIZE);
            const int lab = g_labels8[lcix[i]];
            const int rg = lrix[i];
            out[i * 2 + 0] = __ldcg(&g_heights[(rg * N_CLUSTERS + lab) * BINWIDTH + bl]);
            out[i * 2 + 1] = (bl == br) ? lpIn : lpOut;
        }
    }
}

// ---------------------------------------------------------------------------
extern "C" void kernel_launch(void* const* d_in, const int* in_sizes, int n_in,
                              void* d_out, int out_size)
{
    const float* baseline = (const float*)d_in[0];
    const float* delta    = (const float*)d_in[1];
    const float* inside   = (const float*)d_in[2];
    const int*   regions  = (const int*)d_in[3];
    const int*   coords   = (const int*)d_in[4];
    const int*   lrix     = (const int*)d_in[5];
    const int*   lcix     = (const int*)d_in[6];
    const int*   labels   = (const int*)d_in[7];
    float*       out      = (float*)d_out;

    const int n_roi      = in_sizes[3];
    const int n          = in_sizes[5];
    const int n_cells    = in_sizes[7];
    const int n_regions  = in_sizes[0] / BINWIDTH;
    const int n_clusters = (n_regions > 0) ? (in_sizes[1] / (n_regions * BINWIDTH)) : N_CLUSTERS;

    const int n_rows     = n_roi * n_clusters;
    const int rowBlocks  = (n_rows + 7) / 8;
    const int packBlocks = (n_cells + 1023) / 1024;
    build_kernel<<<rowBlocks + packBlocks, 256>>>(
        baseline, delta, regions, labels, n_rows, n_clusters, rowBlocks, n_cells);

    const int warps  = (n + 127) / 128;
    const int blocks = (warps + 7) / 8;       // 8 warps (256 threads) per block

    cudaLaunchConfig_t cfg = {};
    cfg.gridDim  = dim3((unsigned)blocks, 1, 1);
    cfg.blockDim = dim3(256, 1, 1);
    cfg.dynamicSmemBytes = 0;
    cfg.stream = 0;
    cudaLaunchAttribute at[1];
    at[0].id = cudaLaunchAttributeProgrammaticStreamSerialization;
    at[0].val.programmaticStreamSerializationAllowed = 1;
    cfg.attrs = at;
    cfg.numAttrs = 1;
    cudaError_t e = cudaLaunchKernelEx(&cfg, gather_kernel,
                                       coords, lrix, lcix, inside, out, n);
    if (e != cudaSuccess) {
        gather_kernel<<<blocks, 256>>>(coords, lrix, lcix, inside, out, n);
    }
}